// round 15
// baseline (speedup 1.0000x reference)
#include <cuda_runtime.h>
#include <cuda_bf16.h>
#include <cstdint>

#define Hh    51
#define GP    56          // padded rows per gate
#define LOFF  224         // rows per layer block (4*GP)
#define NRW   448         // total weight rows (2 layers)
#define Mt    64          // batch tile
#define SPB   144         // row stride bytes (64 bf16 data + pad) — conflict-free ldmatrix
#define Tt    2048
#define OTot  2112
#define Bt    8192
#define GRID  148
#define TPB   448         // 14 warps: (pw 0..1) x (jt 0..6)

#define ATILE  (Mt*SPB)                  // 9216
#define OFF_WH 0
#define OFF_WL (OFF_WH + NRW*SPB)        // 64512
#define OFF_A  (OFF_WL + NRW*SPB)        // 129024: [buf][H,L] -> 4 x 9216
#define OFF_PARTS (OFF_A + 4*ATILE)      // 165888: f32[2][14][32]
#define OFF_XS (OFF_PARTS + 2*14*32*4)   // 169472: f32[2][64]
#define SMEM_BYTES (OFF_XS + 2*64*4)     // 169984

static __device__ __forceinline__ uint32_t smem_u32(const void* p){
    uint32_t a;
    asm("{ .reg .u64 t; cvta.to.shared.u64 t, %1; cvt.u32.u64 %0, t; }"
        : "=r"(a) : "l"(p));
    return a;
}

__device__ __forceinline__ void lda(uint32_t (&r)[4], uint32_t base, int mt, int kc, int lane){
    uint32_t addr = base + (uint32_t)((mt*16 + ((lane>>3)&1)*8 + (lane&7))*SPB
                                      + kc*32 + ((lane>>4)&1)*16);
    asm volatile("ldmatrix.sync.aligned.m8n8.x4.shared.b16 {%0,%1,%2,%3}, [%4];"
        : "=r"(r[0]),"=r"(r[1]),"=r"(r[2]),"=r"(r[3]) : "r"(addr));
}
__device__ __forceinline__ void ldb(uint32_t (&r)[2], uint32_t base, int nbase, int kc, int lane){
    int l = lane & 15;
    uint32_t addr = base + (uint32_t)((nbase + (l&7))*SPB + kc*32 + ((l>>3)&1)*16);
    asm volatile("ldmatrix.sync.aligned.m8n8.x2.shared.b16 {%0,%1}, [%2];"
        : "=r"(r[0]),"=r"(r[1]) : "r"(addr));
}
__device__ __forceinline__ void mma_bf16(float (&d)[4], const uint32_t (&a)[4],
                                         const uint32_t (&b)[2]){
    asm volatile("mma.sync.aligned.m16n8k16.row.col.f32.bf16.bf16.f32 "
        "{%0,%1,%2,%3}, {%4,%5,%6,%7}, {%8,%9}, {%0,%1,%2,%3};"
        : "+f"(d[0]),"+f"(d[1]),"+f"(d[2]),"+f"(d[3])
        : "r"(a[0]),"r"(a[1]),"r"(a[2]),"r"(a[3]), "r"(b[0]),"r"(b[1]));
}

// 1-MUFU activations (tanh.approx.f32, sm_75+ base PTX)
__device__ __forceinline__ float tanha(float x){
    float r;
    asm("tanh.approx.f32 %0, %1;" : "=f"(r) : "f"(x));
    return r;
}
__device__ __forceinline__ float sigm(float x){
    return fmaf(0.5f, tanha(0.5f*x), 0.5f);
}
__device__ __forceinline__ float tanh_f(float x){
    return tanha(x);
}

__device__ __forceinline__ void split_sts(char* smem, int off_h, int off_l,
                                          uint32_t o, float v){
    __nv_bfloat16 hi = __float2bfloat16(v);
    float lo = v - __bfloat162float(hi);
    *reinterpret_cast<__nv_bfloat16*>(smem + off_h + o) = hi;
    *reinterpret_cast<__nv_bfloat16*>(smem + off_l + o) = __float2bfloat16(lo);
}

// One layer's GEMM for this warp: D[cb][g][4] = A(hi,lo) x W_L(hi,lo), 3-product split.
template<int L>
__device__ __forceinline__ void layer_mma(float (&D)[2][4][4],
    uint32_t aH, uint32_t aL, uint32_t wH, uint32_t wL,
    int pw, int jt, int lane)
{
    #pragma unroll
    for (int cb = 0; cb < 2; cb++)
        #pragma unroll
        for (int g = 0; g < 4; g++)
            #pragma unroll
            for (int i = 0; i < 4; i++) D[cb][g][i] = 0.f;

    #pragma unroll
    for (int kc = 0; kc < 4; kc++){
        uint32_t ah0[4], al0[4], ah1[4], al1[4];
        lda(ah0, aH, pw*2,   kc, lane);
        lda(al0, aL, pw*2,   kc, lane);
        lda(ah1, aH, pw*2+1, kc, lane);
        lda(al1, aL, pw*2+1, kc, lane);
        #pragma unroll
        for (int g = 0; g < 4; g++){
            int nb_ = L*LOFF + g*GP + jt*8;
            uint32_t bh[2], bl[2];
            ldb(bh, wH, nb_, kc, lane);
            ldb(bl, wL, nb_, kc, lane);
            mma_bf16(D[0][g], ah0, bh);
            mma_bf16(D[0][g], ah0, bl);
            mma_bf16(D[0][g], al0, bh);
            mma_bf16(D[1][g], ah1, bh);
            mma_bf16(D[1][g], ah1, bl);
            mma_bf16(D[1][g], al1, bh);
        }
    }
}

__global__ void __launch_bounds__(TPB, 1)
lstm_hmma_kernel(
    const float* __restrict__ x,
    const float* __restrict__ Wih1, const float* __restrict__ Whh1,
    const float* __restrict__ bih1, const float* __restrict__ bhh1,
    const float* __restrict__ Wih2, const float* __restrict__ Whh2,
    const float* __restrict__ bih2, const float* __restrict__ bhh2,
    const float* __restrict__ Wout, const float* __restrict__ bout,
    float* __restrict__ out)
{
    extern __shared__ char smem[];
    uint32_t sb = smem_u32(smem);
    int tid = threadIdx.x, w = tid >> 5, lane = tid & 31;

    // ---- weights: row n = L*224 + gate*56 + j, K-major (no x column), hi/lo ----
    for (int idx = tid; idx < NRW*64; idx += TPB){
        int n = idx >> 6, k = idx & 63;
        int L = n / LOFF, r = n - L*LOFF;
        int g = r / GP, j = r - g*GP;
        float wv = 0.f;
        if (j < Hh && k < Hh){
            int src = (g*Hh + j)*Hh + k;
            wv = L ? (Wih2[src] + Whh2[src]) : Whh1[src];
        }
        split_sts(smem, OFF_WH, OFF_WL, (uint32_t)(n*SPB + k*2), wv);
    }
    // zero both A buffers (hi+lo)
    for (int idx = tid; idx < 4*ATILE/4; idx += TPB)
        *reinterpret_cast<uint32_t*>(smem + OFF_A + idx*4) = 0u;

    int bstart = (int)(((long long)blockIdx.x       * Bt) / GRID);
    int bend   = (int)(((long long)(blockIdx.x + 1) * Bt) / GRID);
    int nb     = bend - bstart;

    float* xs    = reinterpret_cast<float*>(smem + OFF_XS);     // [2][64]
    float* parts = reinterpret_cast<float*>(smem + OFF_PARTS);  // [2][14*32]
    if (tid < Mt)
        xs[tid] = (tid < nb) ? __ldg(&x[(size_t)(bstart + tid) * Tt]) : 0.f;
    __syncthreads();

    // ---- per-thread mapping ----
    int pw = w / 7, jt = w - pw*7;
    int rgrp = lane >> 2;
    int j0 = jt*8 + 2*(lane & 3);
    int j1 = j0 + 1;

    float b1r[4][2], b2r[4][2], wxr[4][2], wor[2];
    #pragma unroll
    for (int g = 0; g < 4; g++){
        b1r[g][0] = (j0 < Hh) ? (bih1[g*Hh + j0] + bhh1[g*Hh + j0]) : 0.f;
        b1r[g][1] = (j1 < Hh) ? (bih1[g*Hh + j1] + bhh1[g*Hh + j1]) : 0.f;
        b2r[g][0] = (j0 < Hh) ? (bih2[g*Hh + j0] + bhh2[g*Hh + j0]) : 0.f;
        b2r[g][1] = (j1 < Hh) ? (bih2[g*Hh + j1] + bhh2[g*Hh + j1]) : 0.f;
        wxr[g][0] = (j0 < Hh) ? Wih1[g*Hh + j0] : 0.f;
        wxr[g][1] = (j1 < Hh) ? Wih1[g*Hh + j1] : 0.f;
    }
    wor[0] = (j0 < Hh) ? Wout[j0] : 0.f;
    wor[1] = (j1 < Hh) ? Wout[j1] : 0.f;

    float c1[2][2][2];
    #pragma unroll
    for (int a = 0; a < 2; a++)
        #pragma unroll
        for (int b = 0; b < 2; b++)
            #pragma unroll
            for (int c = 0; c < 2; c++) c1[a][b][c] = 0.f;

    float bo = *bout;
    bool ywarp = (jt == 0);
    int ym = pw*32 + lane;
    uint32_t wH = sb + OFF_WH, wL = sb + OFF_WL;

    // ======================= sequence phase: 1 barrier/step =======================
    for (int k = 0; k < Tt; k++){
        int rb = (k+1)&1, wb = k&1;
        uint32_t aHr = sb + OFF_A + (rb*2+0)*ATILE;
        uint32_t aLr = sb + OFF_A + (rb*2+1)*ATILE;
        int aHw = OFF_A + (wb*2+0)*ATILE;
        int aLw = OFF_A + (wb*2+1)*ATILE;

        // y-warps: deferred y(k-2) combine + x(k+1) prefetch
        if (ywarp){
            if (k >= 2){
                float y = bo;
                #pragma unroll
                for (int q = 0; q < 7; q++)
                    y += parts[rb*448 + (pw*7 + q)*32 + lane];
                if (ym < nb) out[(size_t)(bstart + ym)*OTot + (k-2)] = y;
            }
            if (k + 1 < Tt){
                float xv = (ym < nb) ? __ldg(&x[(size_t)(bstart + ym)*Tt + k + 1]) : 0.f;
                xs[rb*64 + ym] = xv;
            }
        }

        float D[2][4][4];

        // ---- emit GEMM (step k-1) + partials ----
        if (k > 0){
            layer_mma<1>(D, aHr, aLr, wH, wL, pw, jt, lane);
            #pragma unroll
            for (int cb = 0; cb < 2; cb++){
                float plo = 0.f, phi = 0.f;
                #pragma unroll
                for (int hf = 0; hf < 2; hf++){
                    #pragma unroll
                    for (int jc = 0; jc < 2; jc++){
                        int e = hf*2 + jc;
                        float gi = D[cb][0][e] + b2r[0][jc];
                        float gf = D[cb][1][e] + b2r[1][jc];
                        float gg = D[cb][2][e] + b2r[2][jc];
                        float go = D[cb][3][e] + b2r[3][jc];
                        float c2 = sigm(gf)*c1[cb][hf][jc] + sigm(gi)*tanh_f(gg);
                        float v  = sigm(go)*tanh_f(c2) * wor[jc];
                        if (hf) phi += v; else plo += v;
                    }
                }
                plo += __shfl_xor_sync(0xffffffffu, plo, 1);
                plo += __shfl_xor_sync(0xffffffffu, plo, 2);
                phi += __shfl_xor_sync(0xffffffffu, phi, 1);
                phi += __shfl_xor_sync(0xffffffffu, phi, 2);
                if ((lane & 3) == 0){
                    parts[wb*448 + w*32 + cb*16 + rgrp]     = plo;
                    parts[wb*448 + w*32 + cb*16 + 8 + rgrp] = phi;
                }
            }
        }

        // ---- layer-1 GEMM (step k) + cell update ----
        layer_mma<0>(D, aHr, aLr, wH, wL, pw, jt, lane);
        #pragma unroll
        for (int cb = 0; cb < 2; cb++){
            int mbase = (pw*2 + cb)*16 + rgrp;
            #pragma unroll
            for (int hf = 0; hf < 2; hf++){
                int m = mbase + hf*8;
                float xm = xs[wb*64 + m];
                #pragma unroll
                for (int jc = 0; jc < 2; jc++){
                    int e = hf*2 + jc;
                    float gi = D[cb][0][e] + b1r[0][jc] + wxr[0][jc]*xm;
                    float gf = D[cb][1][e] + b1r[1][jc] + wxr[1][jc]*xm;
                    float gg = D[cb][2][e] + b1r[2][jc] + wxr[2][jc]*xm;
                    float go = D[cb][3][e] + b1r[3][jc] + wxr[3][jc]*xm;
                    float cn = sigm(gf)*c1[cb][hf][jc] + sigm(gi)*tanh_f(gg);
                    c1[cb][hf][jc] = cn;
                    float hp = sigm(go)*tanh_f(cn);
                    int j = jc ? j1 : j0;
                    split_sts(smem, aHw, aLw, (uint32_t)(m*SPB + j*2), hp);
                }
            }
        }
        __syncthreads();
    }

    // ======================= future phase: autoregressive =======================
    for (int k = Tt; k < OTot; k++){
        int rb = (k+1)&1, wb = k&1;
        uint32_t aHr = sb + OFF_A + (rb*2+0)*ATILE;
        uint32_t aLr = sb + OFF_A + (rb*2+1)*ATILE;
        int aHw = OFF_A + (wb*2+0)*ATILE;
        int aLw = OFF_A + (wb*2+1)*ATILE;

        float D[2][4][4];
        layer_mma<1>(D, aHr, aLr, wH, wL, pw, jt, lane);
        #pragma unroll
        for (int cb = 0; cb < 2; cb++){
            float plo = 0.f, phi = 0.f;
            #pragma unroll
            for (int hf = 0; hf < 2; hf++){
                #pragma unroll
                for (int jc = 0; jc < 2; jc++){
                    int e = hf*2 + jc;
                    float gi = D[cb][0][e] + b2r[0][jc];
                    float gf = D[cb][1][e] + b2r[1][jc];
                    float gg = D[cb][2][e] + b2r[2][jc];
                    float go = D[cb][3][e] + b2r[3][jc];
                    float c2 = sigm(gf)*c1[cb][hf][jc] + sigm(gi)*tanh_f(gg);
                    float v  = sigm(go)*tanh_f(c2) * wor[jc];
                    if (hf) phi += v; else plo += v;
                }
            }
            plo += __shfl_xor_sync(0xffffffffu, plo, 1);
            plo += __shfl_xor_sync(0xffffffffu, plo, 2);
            phi += __shfl_xor_sync(0xffffffffu, phi, 1);
            phi += __shfl_xor_sync(0xffffffffu, phi, 2);
            if ((lane & 3) == 0){
                parts[wb*448 + w*32 + cb*16 + rgrp]     = plo;
                parts[wb*448 + w*32 + cb*16 + 8 + rgrp] = phi;
            }
        }
        // boundary: deferred y(Tt-2) still pending at k==Tt
        if (k == Tt && ywarp){
            float y = bo;
            #pragma unroll
            for (int q = 0; q < 7; q++)
                y += parts[rb*448 + (pw*7 + q)*32 + lane];
            if (ym < nb) out[(size_t)(bstart + ym)*OTot + (k-2)] = y;
        }
        __syncthreads();

        if (ywarp){
            float y = bo;
            #pragma unroll
            for (int q = 0; q < 7; q++)
                y += parts[wb*448 + (pw*7 + q)*32 + lane];
            if (ym < nb) out[(size_t)(bstart + ym)*OTot + (k-1)] = y;
            xs[wb*64 + ym] = y;            // x(k) feedback
        }
        __syncthreads();

        layer_mma<0>(D, aHr, aLr, wH, wL, pw, jt, lane);
        #pragma unroll
        for (int cb = 0; cb < 2; cb++){
            int mbase = (pw*2 + cb)*16 + rgrp;
            #pragma unroll
            for (int hf = 0; hf < 2; hf++){
                int m = mbase + hf*8;
                float xm = xs[wb*64 + m];
                #pragma unroll
                for (int jc = 0; jc < 2; jc++){
                    int e = hf*2 + jc;
                    float gi = D[cb][0][e] + b1r[0][jc] + wxr[0][jc]*xm;
                    float gf = D[cb][1][e] + b1r[1][jc] + wxr[1][jc]*xm;
                    float gg = D[cb][2][e] + b1r[2][jc] + wxr[2][jc]*xm;
                    float go = D[cb][3][e] + b1r[3][jc] + wxr[3][jc]*xm;
                    float cn = sigm(gf)*c1[cb][hf][jc] + sigm(gi)*tanh_f(gg);
                    c1[cb][hf][jc] = cn;
                    float hp = sigm(go)*tanh_f(cn);
                    int j = jc ? j1 : j0;
                    split_sts(smem, aHw, aLw, (uint32_t)(m*SPB + j*2), hp);
                }
            }
        }
        __syncthreads();
    }

    // ======================= tail: emit y(OTot-1) =======================
    {
        int k = OTot;
        int wb = k&1;
        uint32_t aHr = sb + OFF_A + (((k+1)&1)*2+0)*ATILE;
        uint32_t aLr = sb + OFF_A + (((k+1)&1)*2+1)*ATILE;
        float D[2][4][4];
        layer_mma<1>(D, aHr, aLr, wH, wL, pw, jt, lane);
        #pragma unroll
        for (int cb = 0; cb < 2; cb++){
            float plo = 0.f, phi = 0.f;
            #pragma unroll
            for (int hf = 0; hf < 2; hf++){
                #pragma unroll
                for (int jc = 0; jc < 2; jc++){
                    int e = hf*2 + jc;
                    float gi = D[cb][0][e] + b2r[0][jc];
                    float gf = D[cb][1][e] + b2r[1][jc];
                    float gg = D[cb][2][e] + b2r[2][jc];
                    float go = D[cb][3][e] + b2r[3][jc];
                    float c2 = sigm(gf)*c1[cb][hf][jc] + sigm(gi)*tanh_f(gg);
                    float v  = sigm(go)*tanh_f(c2) * wor[jc];
                    if (hf) phi += v; else plo += v;
                }
            }
            plo += __shfl_xor_sync(0xffffffffu, plo, 1);
            plo += __shfl_xor_sync(0xffffffffu, plo, 2);
            phi += __shfl_xor_sync(0xffffffffu, phi, 1);
            phi += __shfl_xor_sync(0xffffffffu, phi, 2);
            if ((lane & 3) == 0){
                parts[wb*448 + w*32 + cb*16 + rgrp]     = plo;
                parts[wb*448 + w*32 + cb*16 + 8 + rgrp] = phi;
            }
        }
        __syncthreads();
        if (ywarp){
            float y = bo;
            #pragma unroll
            for (int q = 0; q < 7; q++)
                y += parts[wb*448 + (pw*7 + q)*32 + lane];
            if (ym < nb) out[(size_t)(bstart + ym)*OTot + (OTot-1)] = y;
        }
    }
}

extern "C" void kernel_launch(void* const* d_in, const int* in_sizes, int n_in,
                              void* d_out, int out_size)
{
    const float* x    = (const float*)d_in[0];
    const float* Wih1 = (const float*)d_in[1];
    const float* Whh1 = (const float*)d_in[2];
    const float* bih1 = (const float*)d_in[3];
    const float* bhh1 = (const float*)d_in[4];
    const float* Wih2 = (const float*)d_in[5];
    const float* Whh2 = (const float*)d_in[6];
    const float* bih2 = (const float*)d_in[7];
    const float* bhh2 = (const float*)d_in[8];
    const float* Wout = (const float*)d_in[9];
    const float* bout = (const float*)d_in[10];
    float* out = (float*)d_out;

    cudaFuncSetAttribute(lstm_hmma_kernel,
                         cudaFuncAttributeMaxDynamicSharedMemorySize, SMEM_BYTES);

    lstm_hmma_kernel<<<GRID, TPB, SMEM_BYTES>>>(
        x, Wih1, Whh1, bih1, bhh1, Wih2, Whh2, bih2, bhh2, Wout, bout, out);
}

// round 17
// speedup vs baseline: 1.4817x; 1.4817x over previous
#include <cuda_runtime.h>
#include <cuda_fp16.h>
#include <cstdint>

#define Hh    51
#define GP    56          // padded rows per gate
#define LOFF  224         // rows per layer block (4*GP)
#define NRW   448         // total weight rows (2 layers)
#define Mt    64          // batch tile
#define SPB   144         // row stride bytes (64 fp16 data + pad) — conflict-free ldmatrix
#define Tt    2048
#define OTot  2112
#define Bt    8192
#define GRID  148
#define TPB   448         // 14 warps: (pw 0..1) x (jt 0..6)
#define LOSC  1024.0f     // W_lo scale (keeps lo terms in fp16 normal range)
#define LOINV (1.0f/1024.0f)

#define ATILE  (Mt*SPB)                  // 9216
#define OFF_WH 0
#define OFF_WL (OFF_WH + NRW*SPB)        // 64512
#define OFF_A  (OFF_WL + NRW*SPB)        // 129024: [buf] -> 2 x 9216 (single fp16 tile)
#define OFF_PARTS (OFF_A + 2*ATILE)      // 147456: f32[2][14][32]
#define OFF_XS (OFF_PARTS + 2*14*32*4)   // 151040: f32[2][64]
#define SMEM_BYTES (OFF_XS + 2*64*4)     // 151552

static __device__ __forceinline__ uint32_t smem_u32(const void* p){
    uint32_t a;
    asm("{ .reg .u64 t; cvta.to.shared.u64 t, %1; cvt.u32.u64 %0, t; }"
        : "=r"(a) : "l"(p));
    return a;
}

__device__ __forceinline__ void lda(uint32_t (&r)[4], uint32_t base, int mt, int kc, int lane){
    uint32_t addr = base + (uint32_t)((mt*16 + ((lane>>3)&1)*8 + (lane&7))*SPB
                                      + kc*32 + ((lane>>4)&1)*16);
    asm volatile("ldmatrix.sync.aligned.m8n8.x4.shared.b16 {%0,%1,%2,%3}, [%4];"
        : "=r"(r[0]),"=r"(r[1]),"=r"(r[2]),"=r"(r[3]) : "r"(addr));
}
__device__ __forceinline__ void ldb(uint32_t (&r)[2], uint32_t base, int nbase, int kc, int lane){
    int l = lane & 15;
    uint32_t addr = base + (uint32_t)((nbase + (l&7))*SPB + kc*32 + ((l>>3)&1)*16);
    asm volatile("ldmatrix.sync.aligned.m8n8.x2.shared.b16 {%0,%1}, [%2];"
        : "=r"(r[0]),"=r"(r[1]) : "r"(addr));
}
__device__ __forceinline__ void mma_f16(float (&d)[4], const uint32_t (&a)[4],
                                        const uint32_t (&b)[2]){
    asm volatile("mma.sync.aligned.m16n8k16.row.col.f32.f16.f16.f32 "
        "{%0,%1,%2,%3}, {%4,%5,%6,%7}, {%8,%9}, {%0,%1,%2,%3};"
        : "+f"(d[0]),"+f"(d[1]),"+f"(d[2]),"+f"(d[3])
        : "r"(a[0]),"r"(a[1]),"r"(a[2]),"r"(a[3]), "r"(b[0]),"r"(b[1]));
}

// proven activations (R14): 2-MUFU forms — do NOT use tanh.approx (R15 regression)
__device__ __forceinline__ float sigm(float x){
    return __fdividef(1.0f, 1.0f + __expf(-x));
}
__device__ __forceinline__ float tanh_f(float x){
    float ax = fabsf(x);
    float e  = __expf(-2.0f * ax);
    float r  = __fdividef(1.0f - e, 1.0f + e);
    return copysignf(r, x);
}

// One layer's GEMM: D[cb][g][4] = A_f16 x (W_hi + W_lo/1024), 2-product split.
template<int L>
__device__ __forceinline__ void layer_mma(float (&D)[2][4][4],
    uint32_t aB, uint32_t wH, uint32_t wL,
    int pw, int jt, int lane)
{
    float Dh[2][4][4], Dl[2][4][4];
    #pragma unroll
    for (int cb = 0; cb < 2; cb++)
        #pragma unroll
        for (int g = 0; g < 4; g++)
            #pragma unroll
            for (int i = 0; i < 4; i++){ Dh[cb][g][i] = 0.f; Dl[cb][g][i] = 0.f; }

    #pragma unroll
    for (int kc = 0; kc < 4; kc++){
        uint32_t a0[4], a1[4];
        lda(a0, aB, pw*2,   kc, lane);
        lda(a1, aB, pw*2+1, kc, lane);
        #pragma unroll
        for (int g = 0; g < 4; g++){
            int nb_ = L*LOFF + g*GP + jt*8;
            uint32_t bh[2], bl[2];
            ldb(bh, wH, nb_, kc, lane);
            ldb(bl, wL, nb_, kc, lane);
            mma_f16(Dh[0][g], a0, bh);
            mma_f16(Dl[0][g], a0, bl);
            mma_f16(Dh[1][g], a1, bh);
            mma_f16(Dl[1][g], a1, bl);
        }
    }
    #pragma unroll
    for (int cb = 0; cb < 2; cb++)
        #pragma unroll
        for (int g = 0; g < 4; g++)
            #pragma unroll
            for (int i = 0; i < 4; i++)
                D[cb][g][i] = fmaf(Dl[cb][g][i], LOINV, Dh[cb][g][i]);
}

__global__ void __launch_bounds__(TPB, 1)
lstm_hmma_kernel(
    const float* __restrict__ x,
    const float* __restrict__ Wih1, const float* __restrict__ Whh1,
    const float* __restrict__ bih1, const float* __restrict__ bhh1,
    const float* __restrict__ Wih2, const float* __restrict__ Whh2,
    const float* __restrict__ bih2, const float* __restrict__ bhh2,
    const float* __restrict__ Wout, const float* __restrict__ bout,
    float* __restrict__ out)
{
    extern __shared__ char smem[];
    uint32_t sb = smem_u32(smem);
    int tid = threadIdx.x, w = tid >> 5, lane = tid & 31;

    // ---- weights: row n = L*224 + gate*56 + j, K-major; fp16 hi + scaled lo ----
    for (int idx = tid; idx < NRW*64; idx += TPB){
        int n = idx >> 6, k = idx & 63;
        int L = n / LOFF, r = n - L*LOFF;
        int g = r / GP, j = r - g*GP;
        float wv = 0.f;
        if (j < Hh && k < Hh){
            int src = (g*Hh + j)*Hh + k;
            wv = L ? (Wih2[src] + Whh2[src]) : Whh1[src];
        }
        __half hi = __float2half(wv);
        __half lo = __float2half((wv - __half2float(hi)) * LOSC);
        uint32_t o = (uint32_t)(n*SPB + k*2);
        *reinterpret_cast<__half*>(smem + OFF_WH + o) = hi;
        *reinterpret_cast<__half*>(smem + OFF_WL + o) = lo;
    }
    // zero both A buffers
    for (int idx = tid; idx < 2*ATILE/4; idx += TPB)
        *reinterpret_cast<uint32_t*>(smem + OFF_A + idx*4) = 0u;

    int bstart = (int)(((long long)blockIdx.x       * Bt) / GRID);
    int bend   = (int)(((long long)(blockIdx.x + 1) * Bt) / GRID);
    int nb     = bend - bstart;

    float* xs    = reinterpret_cast<float*>(smem + OFF_XS);     // [2][64]
    float* parts = reinterpret_cast<float*>(smem + OFF_PARTS);  // [2][14*32]
    if (tid < Mt)
        xs[tid] = (tid < nb) ? __ldg(&x[(size_t)(bstart + tid) * Tt]) : 0.f;
    __syncthreads();

    // ---- per-thread mapping ----
    int pw = w / 7, jt = w - pw*7;
    int rgrp = lane >> 2;
    int j0 = jt*8 + 2*(lane & 3);
    int j1 = j0 + 1;

    float b1r[4][2], b2r[4][2], wxr[4][2], wor[2];
    #pragma unroll
    for (int g = 0; g < 4; g++){
        b1r[g][0] = (j0 < Hh) ? (bih1[g*Hh + j0] + bhh1[g*Hh + j0]) : 0.f;
        b1r[g][1] = (j1 < Hh) ? (bih1[g*Hh + j1] + bhh1[g*Hh + j1]) : 0.f;
        b2r[g][0] = (j0 < Hh) ? (bih2[g*Hh + j0] + bhh2[g*Hh + j0]) : 0.f;
        b2r[g][1] = (j1 < Hh) ? (bih2[g*Hh + j1] + bhh2[g*Hh + j1]) : 0.f;
        wxr[g][0] = (j0 < Hh) ? Wih1[g*Hh + j0] : 0.f;
        wxr[g][1] = (j1 < Hh) ? Wih1[g*Hh + j1] : 0.f;
    }
    wor[0] = (j0 < Hh) ? Wout[j0] : 0.f;
    wor[1] = (j1 < Hh) ? Wout[j1] : 0.f;

    float c1[2][2][2];
    #pragma unroll
    for (int a = 0; a < 2; a++)
        #pragma unroll
        for (int b = 0; b < 2; b++)
            #pragma unroll
            for (int c = 0; c < 2; c++) c1[a][b][c] = 0.f;

    float bo = *bout;
    bool ywarp = (jt == 0);
    int ym = pw*32 + lane;
    uint32_t wH = sb + OFF_WH, wL = sb + OFF_WL;

    // ======================= sequence phase: 1 barrier/step =======================
    for (int k = 0; k < Tt; k++){
        int rb = (k+1)&1, wb = k&1;
        uint32_t aR = sb + OFF_A + rb*ATILE;
        int      aW = OFF_A + wb*ATILE;

        // y-warps: deferred y(k-2) combine + x(k+1) prefetch
        if (ywarp){
            if (k >= 2){
                float y = bo;
                #pragma unroll
                for (int q = 0; q < 7; q++)
                    y += parts[rb*448 + (pw*7 + q)*32 + lane];
                if (ym < nb) out[(size_t)(bstart + ym)*OTot + (k-2)] = y;
            }
            if (k + 1 < Tt){
                float xv = (ym < nb) ? __ldg(&x[(size_t)(bstart + ym)*Tt + k + 1]) : 0.f;
                xs[rb*64 + ym] = xv;
            }
        }

        float D[2][4][4];

        // ---- emit GEMM (step k-1) + partials ----
        if (k > 0){
            layer_mma<1>(D, aR, wH, wL, pw, jt, lane);
            #pragma unroll
            for (int cb = 0; cb < 2; cb++){
                float plo = 0.f, phi = 0.f;
                #pragma unroll
                for (int hf = 0; hf < 2; hf++){
                    #pragma unroll
                    for (int jc = 0; jc < 2; jc++){
                        int e = hf*2 + jc;
                        float gi = D[cb][0][e] + b2r[0][jc];
                        float gf = D[cb][1][e] + b2r[1][jc];
                        float gg = D[cb][2][e] + b2r[2][jc];
                        float go = D[cb][3][e] + b2r[3][jc];
                        float c2 = sigm(gf)*c1[cb][hf][jc] + sigm(gi)*tanh_f(gg);
                        float v  = sigm(go)*tanh_f(c2) * wor[jc];
                        if (hf) phi += v; else plo += v;
                    }
                }
                plo += __shfl_xor_sync(0xffffffffu, plo, 1);
                plo += __shfl_xor_sync(0xffffffffu, plo, 2);
                phi += __shfl_xor_sync(0xffffffffu, phi, 1);
                phi += __shfl_xor_sync(0xffffffffu, phi, 2);
                if ((lane & 3) == 0){
                    parts[wb*448 + w*32 + cb*16 + rgrp]     = plo;
                    parts[wb*448 + w*32 + cb*16 + 8 + rgrp] = phi;
                }
            }
        }

        // ---- layer-1 GEMM (step k) + cell update ----
        layer_mma<0>(D, aR, wH, wL, pw, jt, lane);
        #pragma unroll
        for (int cb = 0; cb < 2; cb++){
            int mbase = (pw*2 + cb)*16 + rgrp;
            #pragma unroll
            for (int hf = 0; hf < 2; hf++){
                int m = mbase + hf*8;
                float xm = xs[wb*64 + m];
                #pragma unroll
                for (int jc = 0; jc < 2; jc++){
                    int e = hf*2 + jc;
                    float gi = D[cb][0][e] + b1r[0][jc] + wxr[0][jc]*xm;
                    float gf = D[cb][1][e] + b1r[1][jc] + wxr[1][jc]*xm;
                    float gg = D[cb][2][e] + b1r[2][jc] + wxr[2][jc]*xm;
                    float go = D[cb][3][e] + b1r[3][jc] + wxr[3][jc]*xm;
                    float cn = sigm(gf)*c1[cb][hf][jc] + sigm(gi)*tanh_f(gg);
                    c1[cb][hf][jc] = cn;
                    float hp = sigm(go)*tanh_f(cn);
                    int j = jc ? j1 : j0;
                    *reinterpret_cast<__half*>(smem + aW + (uint32_t)(m*SPB + j*2))
                        = __float2half(hp);
                }
            }
        }
        __syncthreads();
    }

    // ======================= future phase: autoregressive =======================
    for (int k = Tt; k < OTot; k++){
        int rb = (k+1)&1, wb = k&1;
        uint32_t aR = sb + OFF_A + rb*ATILE;
        int      aW = OFF_A + wb*ATILE;

        float D[2][4][4];
        layer_mma<1>(D, aR, wH, wL, pw, jt, lane);
        #pragma unroll
        for (int cb = 0; cb < 2; cb++){
            float plo = 0.f, phi = 0.f;
            #pragma unroll
            for (int hf = 0; hf < 2; hf++){
                #pragma unroll
                for (int jc = 0; jc < 2; jc++){
                    int e = hf*2 + jc;
                    float gi = D[cb][0][e] + b2r[0][jc];
                    float gf = D[cb][1][e] + b2r[1][jc];
                    float gg = D[cb][2][e] + b2r[2][jc];
                    float go = D[cb][3][e] + b2r[3][jc];
                    float c2 = sigm(gf)*c1[cb][hf][jc] + sigm(gi)*tanh_f(gg);
                    float v  = sigm(go)*tanh_f(c2) * wor[jc];
                    if (hf) phi += v; else plo += v;
                }
            }
            plo += __shfl_xor_sync(0xffffffffu, plo, 1);
            plo += __shfl_xor_sync(0xffffffffu, plo, 2);
            phi += __shfl_xor_sync(0xffffffffu, phi, 1);
            phi += __shfl_xor_sync(0xffffffffu, phi, 2);
            if ((lane & 3) == 0){
                parts[wb*448 + w*32 + cb*16 + rgrp]     = plo;
                parts[wb*448 + w*32 + cb*16 + 8 + rgrp] = phi;
            }
        }
        // boundary: deferred y(Tt-2) still pending at k==Tt
        if (k == Tt && ywarp){
            float y = bo;
            #pragma unroll
            for (int q = 0; q < 7; q++)
                y += parts[rb*448 + (pw*7 + q)*32 + lane];
            if (ym < nb) out[(size_t)(bstart + ym)*OTot + (k-2)] = y;
        }
        __syncthreads();

        if (ywarp){
            float y = bo;
            #pragma unroll
            for (int q = 0; q < 7; q++)
                y += parts[wb*448 + (pw*7 + q)*32 + lane];
            if (ym < nb) out[(size_t)(bstart + ym)*OTot + (k-1)] = y;
            xs[wb*64 + ym] = y;            // x(k) feedback
        }
        __syncthreads();

        layer_mma<0>(D, aR, wH, wL, pw, jt, lane);
        #pragma unroll
        for (int cb = 0; cb < 2; cb++){
            int mbase = (pw*2 + cb)*16 + rgrp;
            #pragma unroll
            for (int hf = 0; hf < 2; hf++){
                int m = mbase + hf*8;
                float xm = xs[wb*64 + m];
                #pragma unroll
                for (int jc = 0; jc < 2; jc++){
                    int e = hf*2 + jc;
                    float gi = D[cb][0][e] + b1r[0][jc] + wxr[0][jc]*xm;
                    float gf = D[cb][1][e] + b1r[1][jc] + wxr[1][jc]*xm;
                    float gg = D[cb][2][e] + b1r[2][jc] + wxr[2][jc]*xm;
                    float go = D[cb][3][e] + b1r[3][jc] + wxr[3][jc]*xm;
                    float cn = sigm(gf)*c1[cb][hf][jc] + sigm(gi)*tanh_f(gg);
                    c1[cb][hf][jc] = cn;
                    float hp = sigm(go)*tanh_f(cn);
                    int j = jc ? j1 : j0;
                    *reinterpret_cast<__half*>(smem + aW + (uint32_t)(m*SPB + j*2))
                        = __float2half(hp);
                }
            }
        }
        __syncthreads();
    }

    // ======================= tail: emit y(OTot-1) =======================
    {
        int k = OTot;
        int wb = k&1;
        uint32_t aR = sb + OFF_A + ((k+1)&1)*ATILE;
        float D[2][4][4];
        layer_mma<1>(D, aR, wH, wL, pw, jt, lane);
        #pragma unroll
        for (int cb = 0; cb < 2; cb++){
            float plo = 0.f, phi = 0.f;
            #pragma unroll
            for (int hf = 0; hf < 2; hf++){
                #pragma unroll
                for (int jc = 0; jc < 2; jc++){
                    int e = hf*2 + jc;
                    float gi = D[cb][0][e] + b2r[0][jc];
                    float gf = D[cb][1][e] + b2r[1][jc];
                    float gg = D[cb][2][e] + b2r[2][jc];
                    float go = D[cb][3][e] + b2r[3][jc];
                    float c2 = sigm(gf)*c1[cb][hf][jc] + sigm(gi)*tanh_f(gg);
                    float v  = sigm(go)*tanh_f(c2) * wor[jc];
                    if (hf) phi += v; else plo += v;
                }
            }
            plo += __shfl_xor_sync(0xffffffffu, plo, 1);
            plo += __shfl_xor_sync(0xffffffffu, plo, 2);
            phi += __shfl_xor_sync(0xffffffffu, phi, 1);
            phi += __shfl_xor_sync(0xffffffffu, phi, 2);
            if ((lane & 3) == 0){
                parts[wb*448 + w*32 + cb*16 + rgrp]     = plo;
                parts[wb*448 + w*32 + cb*16 + 8 + rgrp] = phi;
            }
        }
        __syncthreads();
        if (ywarp){
            float y = bo;
            #pragma unroll
            for (int q = 0; q < 7; q++)
                y += parts[wb*448 + (pw*7 + q)*32 + lane];
            if (ym < nb) out[(size_t)(bstart + ym)*OTot + (OTot-1)] = y;
        }
    }
}

extern "C" void kernel_launch(void* const* d_in, const int* in_sizes, int n_in,
                              void* d_out, int out_size)
{
    const float* x    = (const float*)d_in[0];
    const float* Wih1 = (const float*)d_in[1];
    const float* Whh1 = (const float*)d_in[2];
    const float* bih1 = (const float*)d_in[3];
    const float* bhh1 = (const float*)d_in[4];
    const float* Wih2 = (const float*)d_in[5];
    const float* Whh2 = (const float*)d_in[6];
    const float* bih2 = (const float*)d_in[7];
    const float* bhh2 = (const float*)d_in[8];
    const float* Wout = (const float*)d_in[9];
    const float* bout = (const float*)d_in[10];
    float* out = (float*)d_out;

    cudaFuncSetAttribute(lstm_hmma_kernel,
                         cudaFuncAttributeMaxDynamicSharedMemorySize, SMEM_BYTES);

    lstm_hmma_kernel<<<GRID, TPB, SMEM_BYTES>>>(
        x, Wih1, Whh1, bih1, bhh1, Wih2, Whh2, bih2, bhh2, Wout, bout, out);
}